// round 2
// baseline (speedup 1.0000x reference)
#include <cuda_runtime.h>
#include <cuda_bf16.h>

// LogSumExpPooling2D: x [8,256,256,64] f32 NHWC -> out [1,128,128,64]
// out[ho,wo,c] = (1/100) * log( sum_{n,dh,dw} exp(100 * x[n,2ho+dh,2wo+dw,c]) )
//
// One warp per output pixel (ho,wo). Lanes 0..15 handle the even-w pixel's 16
// float4 channel groups, lanes 16..31 the odd-w pixel. 16 fully-coalesced
// LDG.128 per thread (8 n x 2 dh), max shared across the dw lane-pair via
// shfl.xor(16), then exp-sum, merge, write.

#define LSE_SCALE 100.0f
#define INV_SCALE 0.01f

__global__ __launch_bounds__(256)
void lse_pool_kernel(const float* __restrict__ x, float* __restrict__ out)
{
    const int warp = (blockIdx.x * 256 + threadIdx.x) >> 5;  // 0..16383
    const int lane = threadIdx.x & 31;
    const int wo   = warp & 127;
    const int ho   = warp >> 7;
    const int dw   = lane >> 4;   // 0: even w pixel, 1: odd w pixel
    const int j    = lane & 15;   // float4 index within 64 channels

    // float4 strides: w -> 16, h -> 256*64/4 = 4096, n -> 256*256*64/4 = 1048576
    const float4* __restrict__ xb = reinterpret_cast<const float4*>(x)
        + ((size_t)(2 * ho) * 4096 + (size_t)(2 * wo + dw) * 16 + (size_t)j);

    // Front-batched loads: 16 independent LDG.128 in flight per thread.
    float4 v[16];
#pragma unroll
    for (int n = 0; n < 8; ++n) {
#pragma unroll
        for (int dh = 0; dh < 2; ++dh) {
            v[n * 2 + dh] = xb[(size_t)n * 1048576 + (size_t)dh * 4096];
        }
    }

    // Phase 1: per-channel max over the 16 local values.
    float4 m = v[0];
#pragma unroll
    for (int i = 1; i < 16; ++i) {
        m.x = fmaxf(m.x, v[i].x);
        m.y = fmaxf(m.y, v[i].y);
        m.z = fmaxf(m.z, v[i].z);
        m.w = fmaxf(m.w, v[i].w);
    }
    // Share max across the dw lane-pair so both halves use the same reference.
    m.x = fmaxf(m.x, __shfl_xor_sync(0xffffffffu, m.x, 16));
    m.y = fmaxf(m.y, __shfl_xor_sync(0xffffffffu, m.y, 16));
    m.z = fmaxf(m.z, __shfl_xor_sync(0xffffffffu, m.z, 16));
    m.w = fmaxf(m.w, __shfl_xor_sync(0xffffffffu, m.w, 16));

    // Phase 2: sum of exp(100*(v - m)).
    float4 s = make_float4(0.f, 0.f, 0.f, 0.f);
#pragma unroll
    for (int i = 0; i < 16; ++i) {
        s.x += __expf(LSE_SCALE * (v[i].x - m.x));
        s.y += __expf(LSE_SCALE * (v[i].y - m.y));
        s.z += __expf(LSE_SCALE * (v[i].z - m.z));
        s.w += __expf(LSE_SCALE * (v[i].w - m.w));
    }
    // Merge the two w-halves (same max -> plain add).
    s.x += __shfl_xor_sync(0xffffffffu, s.x, 16);
    s.y += __shfl_xor_sync(0xffffffffu, s.y, 16);
    s.z += __shfl_xor_sync(0xffffffffu, s.z, 16);
    s.w += __shfl_xor_sync(0xffffffffu, s.w, 16);

    if (dw == 0) {
        float4 o;
        o.x = m.x + __logf(s.x) * INV_SCALE;
        o.y = m.y + __logf(s.y) * INV_SCALE;
        o.z = m.z + __logf(s.z) * INV_SCALE;
        o.w = m.w + __logf(s.w) * INV_SCALE;
        reinterpret_cast<float4*>(out)[(size_t)(ho * 128 + wo) * 16 + j] = o;
    }
}

extern "C" void kernel_launch(void* const* d_in, const int* in_sizes, int n_in,
                              void* d_out, int out_size)
{
    const float* x = (const float*)d_in[0];
    float* out = (float*)d_out;
    // 128*128 output pixels, 1 warp each, 8 warps per 256-thread block.
    lse_pool_kernel<<<2048, 256>>>(x, out);
}